// round 6
// baseline (speedup 1.0000x reference)
#include <cuda_runtime.h>

#define TT    65536
#define NB3   21845          /* 3*NB3 = 65535 serial 3-step blocks */
#define NP    21846          /* post blocks */
#define SD    100
#define HID   8
#define NOBS  12
#define DTC   0.01f
#define GQ    8
#define PRE_CTAS  ((NB3 + GQ - 1) / GQ)
#define POST_CTAS ((NP  + GQ - 1) / GQ)

__device__ __forceinline__ unsigned long long pack2(float lo, float hi) {
    unsigned long long r;
    asm("mov.b64 %0, {%1, %2};" : "=l"(r) : "f"(lo), "f"(hi));
    return r;
}
__device__ __forceinline__ void unpack2(unsigned long long v, float& lo, float& hi) {
    asm("mov.b64 {%0, %1}, %2;" : "=f"(lo), "=f"(hi) : "l"(v));
}
__device__ __forceinline__ void fma2(unsigned long long& acc, unsigned long long a, unsigned long long b) {
    asm("fma.rn.f32x2 %0, %1, %2, %0;" : "+l"(acc) : "l"(a), "l"(b));
}
__device__ __forceinline__ void add2(unsigned long long& acc, unsigned long long b) {
    asm("add.rn.f32x2 %0, %0, %1;" : "+l"(acc) : "l"(b));
}
__device__ __forceinline__ float tanh_hw(float x) {
    float r;
    asm("tanh.approx.f32 %0, %1;" : "=f"(r) : "f"(x));
    return r;
}

// ------------------------- device scratch -------------------------
__device__ float g_R[128 * 124];         // per-lane composite rows for serial dot
__device__ float g_At4[SD * SD];         // A in float4-interleaved matvec layout
__device__ float g_A2[SD * SD];          // A^2 (setup temp)
__device__ float g_U1[SD * HID];         // dt A W2
__device__ float g_U2[SD * HID];         // dt A^2 W2
__device__ float g_V0[64];               // dt W1 W2
__device__ float g_V1[64];               // dt W1 A W2
__device__ float g_P3[(size_t)NB3 * SD];
__device__ float g_Qq[(size_t)NB3 * 24]; // q0|q1|q2 per block
__device__ float g_G[(size_t)(NB3 + 1) * SD];   // g_{3b}
__device__ float g_h[(size_t)(TT + 2) * HID];   // h_t rows 0..65537

// ============================================================================
// 1) setup (1 CTA): composite matrices, At4 layout, h1/h2, initial rows
// ============================================================================
__global__ void __launch_bounds__(128, 1) setup_kernel(
    const float* __restrict__ A,  const float* __restrict__ Bw,
    const float* __restrict__ W1, const float* __restrict__ b1,
    const float* __restrict__ W2, const float* __restrict__ b2,
    const float* __restrict__ c0, const float* __restrict__ w,
    const float* __restrict__ u)
{
    __shared__ float As[SD * SD];     // 40000 B
    __shared__ float W2d[SD * HID];   // dt*W2
    __shared__ float W1s[SD * HID];   // W1, later U1, later U2 (staging reuse)
    __shared__ float cA[SD];
    __shared__ float cB[SD];
    __shared__ float h1s[HID];

    const int tid = threadIdx.x;

    // P0: stage inputs, init rows
    for (int i = tid; i < SD * SD; i += 128) As[i] = A[i];
    for (int i = tid; i < SD * HID; i += 128) W2d[i] = DTC * W2[i];
    for (int i = tid; i < SD * HID; i += 128) W1s[i] = W1[i];   // W1 is 8x100 = 800
    if (tid < SD) { cA[tid] = c0[tid]; g_G[tid] = c0[tid]; }
    if (tid < HID) g_h[tid] = 0.f;                              // h_0 = 0
    for (int o = tid; o < 4 * 124; o += 128) g_R[100 * 124 + o] = 0.f; // rows 100-103
    __syncthreads();
    for (int o = tid; o < SD * SD; o += 128) {
        int j4 = o / 400, rem = o % 400, i = rem / 4, r = rem % 4;
        g_At4[o] = As[i * SD + 4 * j4 + r];
    }

    // P0.5: cB = A c0 + IN_0 (no h term yet);  h1 = tanh(W1 c0 + b1)
    if (tid < SD) {
        const int i = tid;
        float s = Bw[i * 2] * w[0] + Bw[i * 2 + 1] * w[1] + u[i] + DTC * b2[i];
        for (int j = 0; j < SD; j++) s += As[i * SD + j] * cA[j];
        cB[i] = s;
    } else if (tid >= 104 && tid < 112) {
        const int z = tid - 104;
        float s = b1[z];
        for (int k = 0; k < SD; k++) s += W1s[z * SD + k] * cA[k];
        float h1 = tanh_hw(s);
        h1s[z] = h1;
        g_h[HID + z] = h1;
    }
    __syncthreads();
    // P0.6: cB += dtW2 h1  (now cB = c_1)
    if (tid < SD) {
        float s = cB[tid];
#pragma unroll
        for (int z = 0; z < HID; z++) s += W2d[tid * HID + z] * h1s[z];
        cB[tid] = s;
    }
    __syncthreads();
    // P0.7: h2 = tanh(W1 c1 + b1)
    if (tid >= 104 && tid < 112) {
        const int z = tid - 104;
        float s = b1[z];
        for (int k = 0; k < SD; k++) s += W1s[z * SD + k] * cB[k];
        g_h[2 * HID + z] = tanh_hw(s);
    }
    __syncthreads();

    // persistent per-lane arrays across phases
    float accA2[SD];
    float u1r[HID], u2r[HID];
    float wa[SD], wb[SD];
    float v0r[HID], v1r[HID], v2r[HID], v3r[HID], v4r[HID];

    // P1: A^2 rows + U1 (g lanes);  W1A + V0 (h lanes)
    if (tid < SD) {
        const int i = tid;
#pragma unroll
        for (int jj = 0; jj < SD; jj++) accA2[jj] = 0.f;
#pragma unroll
        for (int z = 0; z < HID; z++) u1r[z] = 0.f;
        for (int j = 0; j < SD; j++) {
            const float a = As[i * SD + j];
#pragma unroll
            for (int jj = 0; jj < SD; jj++) accA2[jj] += a * As[j * SD + jj];
#pragma unroll
            for (int z = 0; z < HID; z++) u1r[z] += a * W2d[j * HID + z];
        }
        for (int jj = 0; jj < SD; jj++) g_A2[i * SD + jj] = accA2[jj];
#pragma unroll
        for (int z = 0; z < HID; z++) g_U1[i * HID + z] = u1r[z];
    } else if (tid >= 104 && tid < 112) {
        const int z = tid - 104;
#pragma unroll
        for (int jj = 0; jj < SD; jj++) wa[jj] = 0.f;
#pragma unroll
        for (int zz = 0; zz < HID; zz++) v0r[zz] = 0.f;
        for (int k = 0; k < SD; k++) {
            const float wv = W1s[z * SD + k];
#pragma unroll
            for (int jj = 0; jj < SD; jj++) wa[jj] += wv * As[k * SD + jj];
#pragma unroll
            for (int zz = 0; zz < HID; zz++) v0r[zz] += wv * W2d[k * HID + zz];
        }
#pragma unroll
        for (int zz = 0; zz < HID; zz++) g_V0[z * HID + zz] = v0r[zz];
    }
    __syncthreads();
    // stage U1 into W1s
    for (int o = tid; o < SD * HID; o += 128) W1s[o] = g_U1[o];
    __syncthreads();

    // P2: A^3 rows -> g_R[0..99];  U2 = A U1;  h lanes: V1, wa2 = W1A^2
    if (tid < SD) {
        const int i = tid;
        float acc3[SD];
#pragma unroll
        for (int jj = 0; jj < SD; jj++) acc3[jj] = 0.f;
#pragma unroll
        for (int z = 0; z < HID; z++) u2r[z] = 0.f;
        for (int j = 0; j < SD; j++) {
            const float a2 = accA2[j];
            const float a1 = As[i * SD + j];
#pragma unroll
            for (int jj = 0; jj < SD; jj++) acc3[jj] += a2 * As[j * SD + jj];
#pragma unroll
            for (int z = 0; z < HID; z++) u2r[z] += a1 * W1s[j * HID + z];
        }
        for (int jj = 0; jj < SD; jj++) g_R[i * 124 + jj] = acc3[jj];
#pragma unroll
        for (int z = 0; z < HID; z++) g_U2[i * HID + z] = u2r[z];
    } else if (tid >= 104 && tid < 112) {
        const int z = tid - 104;
#pragma unroll
        for (int jj = 0; jj < SD; jj++) wb[jj] = 0.f;
#pragma unroll
        for (int zz = 0; zz < HID; zz++) v1r[zz] = 0.f;
        for (int k = 0; k < SD; k++) {
            const float wv = wa[k];
#pragma unroll
            for (int jj = 0; jj < SD; jj++) wb[jj] += wv * As[k * SD + jj];   // wb = W1A^2
#pragma unroll
            for (int zz = 0; zz < HID; zz++) v1r[zz] += wv * W2d[k * HID + zz];
        }
#pragma unroll
        for (int zz = 0; zz < HID; zz++) g_V1[z * HID + zz] = v1r[zz];
    }
    __syncthreads();
    // stage U2 into W1s
    for (int o = tid; o < SD * HID; o += 128) W1s[o] = g_U2[o];
    __syncthreads();

    // P3: U3 = A U2; assemble g rows tail.  h lanes: V2, wa3, V3, wa4, V4 + rows.
    if (tid < SD) {
        const int i = tid;
        float u3r[HID];
#pragma unroll
        for (int z = 0; z < HID; z++) u3r[z] = 0.f;
        for (int j = 0; j < SD; j++) {
            const float a1 = As[i * SD + j];
#pragma unroll
            for (int z = 0; z < HID; z++) u3r[z] += a1 * W1s[j * HID + z];
        }
#pragma unroll
        for (int z = 0; z < HID; z++) {
            g_R[i * 124 + 100 + z] = u3r[z];
            g_R[i * 124 + 108 + z] = u2r[z];
            g_R[i * 124 + 116 + z] = u1r[z];
        }
    } else if (tid >= 104 && tid < 112) {
        const int z = tid - 104;
        // V2 from wb (= W1A^2); wa3 = wb A; V3; wa4 = wa3 A; V4
#pragma unroll
        for (int zz = 0; zz < HID; zz++) v2r[zz] = 0.f;
        for (int k = 0; k < SD; k++) {
            const float wv = wb[k];
#pragma unroll
            for (int zz = 0; zz < HID; zz++) v2r[zz] += wv * W2d[k * HID + zz];
        }
        float wa3[SD];
#pragma unroll
        for (int jj = 0; jj < SD; jj++) wa3[jj] = 0.f;
        for (int k = 0; k < SD; k++) {
            const float wv = wb[k];
#pragma unroll
            for (int jj = 0; jj < SD; jj++) wa3[jj] += wv * As[k * SD + jj];
        }
#pragma unroll
        for (int zz = 0; zz < HID; zz++) v3r[zz] = 0.f;
        float wa4[SD];
#pragma unroll
        for (int jj = 0; jj < SD; jj++) wa4[jj] = 0.f;
        for (int k = 0; k < SD; k++) {
            const float wv = wa3[k];
#pragma unroll
            for (int zz = 0; zz < HID; zz++) v3r[zz] += wv * W2d[k * HID + zz];
#pragma unroll
            for (int jj = 0; jj < SD; jj++) wa4[jj] += wv * As[k * SD + jj];
        }
#pragma unroll
        for (int zz = 0; zz < HID; zz++) v4r[zz] = 0.f;
        for (int k = 0; k < SD; k++) {
            const float wv = wa4[k];
#pragma unroll
            for (int zz = 0; zz < HID; zz++) v4r[zz] += wv * W2d[k * HID + zz];
        }
        // group0 row (tid 104+z): [W1A^2 | V2 | V1 | V0]
        float* r0 = g_R + (104 + z) * 124;
        for (int jj = 0; jj < SD; jj++) r0[jj] = wb[jj];
#pragma unroll
        for (int zz = 0; zz < HID; zz++) {
            r0[100 + zz] = v2r[zz]; r0[108 + zz] = v1r[zz]; r0[116 + zz] = v0r[zz];
        }
        // group1 row (112+z): [W1A^3 | V3 | V2 | V1]
        float* r1 = g_R + (112 + z) * 124;
        for (int jj = 0; jj < SD; jj++) r1[jj] = wa3[jj];
#pragma unroll
        for (int zz = 0; zz < HID; zz++) {
            r1[100 + zz] = v3r[zz]; r1[108 + zz] = v2r[zz]; r1[116 + zz] = v1r[zz];
        }
        // group2 row (120+z): [W1A^4 | V4 | V3 | V2]
        float* r2 = g_R + (120 + z) * 124;
        for (int jj = 0; jj < SD; jj++) r2[jj] = wa4[jj];
#pragma unroll
        for (int zz = 0; zz < HID; zz++) {
            r2[100 + zz] = v4r[zz]; r2[108 + zz] = v3r[zz]; r2[116 + zz] = v2r[zz];
        }
    }
}

// float4 matvec: out_i = sum_j A[i][j] v[j]
__device__ __forceinline__ float matvec100(const float4* at4s, const float4* v4, int i) {
    float acc = 0.f;
#pragma unroll
    for (int j4 = 0; j4 < 25; j4++) {
        float4 m = at4s[j4 * SD + i];
        float4 x = v4[j4];
        acc = fmaf(m.x, x.x, acc); acc = fmaf(m.y, x.y, acc);
        acc = fmaf(m.z, x.z, acc); acc = fmaf(m.w, x.w, acc);
    }
    return acc;
}

// ============================================================================
// 2) precomp: P_b, q0_b, q1_b, q2_b — GQ blocks per CTA, A staged once
// ============================================================================
__global__ void __launch_bounds__(128, 1) precomp_kernel(
    const float* __restrict__ w, const float* __restrict__ u,
    const float* __restrict__ Bw, const float* __restrict__ W1,
    const float* __restrict__ b1, const float* __restrict__ b2)
{
    __shared__ __align__(16) float4 at4s[SD * 25];
    __shared__ float W1sm[SD * HID];
    __shared__ __align__(16) float va[SD];
    __shared__ __align__(16) float vb[SD];

    const int tid = threadIdx.x;
    const float4* gAt4 = reinterpret_cast<const float4*>(g_At4);
    for (int o = tid; o < SD * 25; o += 128) at4s[o] = gAt4[o];
    for (int o = tid; o < SD * HID; o += 128) W1sm[o] = W1[o];

    float bwx = 0.f, bwy = 0.f, db2 = 0.f;
    if (tid < SD) { bwx = Bw[tid * 2]; bwy = Bw[tid * 2 + 1]; db2 = DTC * b2[tid]; }
    float b1z = 0.f;
    if (tid >= 104 && tid < 112) b1z = b1[tid - 104];
    __syncthreads();

    const float4* va4 = reinterpret_cast<const float4*>(va);
    const float4* vb4 = reinterpret_cast<const float4*>(vb);

    for (int gi = 0; gi < GQ; gi++) {
        const int b = blockIdx.x * GQ + gi;
        const bool act = (b < NB3);
        const int bc = act ? b : (NB3 - 1);
        const size_t k = 3 * (size_t)bc;

        // va = IN_k
        if (tid < SD)
            va[tid] = bwx * w[2 * k] + bwy * w[2 * k + 1] + u[k * SD + tid] + db2;
        __syncthreads();
        // vb = A va + IN_{k+1}
        if (tid < SD)
            vb[tid] = matvec100(at4s, va4, tid)
                    + bwx * w[2 * k + 2] + bwy * w[2 * k + 3] + u[(k + 1) * SD + tid] + db2;
        __syncthreads();
        // vc = A vb + IN_{k+2} (= P);  q0 = W1 vb + b1
        float vcv = 0.f;
        if (tid < SD)
            vcv = matvec100(at4s, vb4, tid)
                + bwx * w[2 * k + 4] + bwy * w[2 * k + 5] + u[(k + 2) * SD + tid] + db2;
        else if (tid >= 104 && tid < 112) {
            const int z = tid - 104;
            float s = b1z;
#pragma unroll 4
            for (int j = 0; j < SD; j++) s += W1sm[z * SD + j] * vb[j];
            if (act) g_Qq[(size_t)b * 24 + z] = s;
        }
        __syncthreads();
        if (tid < SD) {
            va[tid] = vcv;
            if (act) g_P3[(size_t)b * SD + tid] = vcv;
        }
        __syncthreads();
        // vd = A P + IN_{k+3};  q1 = W1 P + b1
        float vdv = 0.f;
        if (tid < SD)
            vdv = matvec100(at4s, va4, tid)
                + bwx * w[2 * k + 6] + bwy * w[2 * k + 7] + u[(k + 3) * SD + tid] + db2;
        else if (tid >= 104 && tid < 112) {
            const int z = tid - 104;
            float s = b1z;
#pragma unroll 4
            for (int j = 0; j < SD; j++) s += W1sm[z * SD + j] * va[j];
            if (act) g_Qq[(size_t)b * 24 + 8 + z] = s;
        }
        __syncthreads();
        if (tid < SD) vb[tid] = vdv;
        __syncthreads();
        // q2 = W1 vd + b1
        if (tid >= 104 && tid < 112) {
            const int z = tid - 104;
            float s = b1z;
#pragma unroll 4
            for (int j = 0; j < SD; j++) s += W1sm[z * SD + j] * vb[j];
            if (act) g_Qq[(size_t)b * 24 + 16 + z] = s;
        }
        __syncthreads();
    }
}

// ============================================================================
// 3) serial: 21845 blocks of 3 steps, 1 CTA x 128 threads, ONE barrier/block.
//    S = [g(100) | h_k(8) | h_{k+1}(8) | h_{k+2}(8)] = 124 floats.
//    h chain lives entirely in warp 3 via shfl (no mid-block barrier).
// ============================================================================
__global__ void __launch_bounds__(128, 1) serial_kernel(const float* __restrict__ c0)
{
    __shared__ __align__(16) float sbuf[2][128];

    const int tid = threadIdx.x;
    const bool isG = (tid < SD);
    const bool w3  = (tid >= 96);

    // init S_0 = [c0 | h0=0 | h1 | h2]
    if (tid < SD)            sbuf[0][tid] = c0[tid];
    else if (tid < 108)      sbuf[0][tid] = 0.f;                       // h0 + pad
    else if (tid < 116)      sbuf[0][tid] = g_h[HID + (tid - 108)];    // h1
    else if (tid < 124)      sbuf[0][tid] = g_h[2 * HID + (tid - 116)];// h2
    else                     sbuf[0][tid] = 0.f;
    sbuf[1][tid] = 0.f;

    // composite row
    unsigned long long rva[62];
    {
        const float* Rr = g_R + tid * 124;
#pragma unroll
        for (int q = 0; q < 62; q++) rva[q] = pack2(Rr[2 * q], Rr[2 * q + 1]);
    }
    // coupling matrices (zero except chain groups 1,2)
    float cpA[8], cpB[8];
#pragma unroll
    for (int j = 0; j < 8; j++) { cpA[j] = 0.f; cpB[j] = 0.f; }
    if (tid >= 112 && tid < 120) {
        const int z = tid - 112;
#pragma unroll
        for (int j = 0; j < 8; j++) cpA[j] = g_V0[z * 8 + j];
    } else if (tid >= 120) {
        const int z = tid - 120;
#pragma unroll
        for (int j = 0; j < 8; j++) { cpA[j] = g_V1[z * 8 + j]; cpB[j] = g_V0[z * 8 + j]; }
    }
    __syncthreads();

    // depth-2 prefetch of P / q
    float pc = 0.f, pn = 0.f;
    if (isG) { pc = g_P3[tid]; pn = g_P3[SD + tid]; }
    else if (tid >= 104) { pc = g_Qq[tid - 104]; pn = g_Qq[24 + (tid - 104)]; }

    int p = 0;
    for (int b = 0; b < NB3; b++) {
        const int bn = (b + 2 < NB3) ? (b + 2) : (NB3 - 1);
        float pn2 = 0.f;
        if (isG) pn2 = __ldcg(&g_P3[(size_t)bn * SD + tid]);
        else if (tid >= 104) pn2 = __ldcg(&g_Qq[(size_t)bn * 24 + (tid - 104)]);

        // 124-long dot vs S_b
        unsigned long long a0 = 0ull, a1 = 0ull, a2 = 0ull, a3 = 0ull;
        const ulonglong2* sp = reinterpret_cast<const ulonglong2*>(sbuf[p]);
#pragma unroll
        for (int q = 0; q < 31; q++) {
            ulonglong2 gg = sp[q];
            if (q & 1) { fma2(a2, rva[2 * q], gg.x); fma2(a3, rva[2 * q + 1], gg.y); }
            else       { fma2(a0, rva[2 * q], gg.x); fma2(a1, rva[2 * q + 1], gg.y); }
        }
        add2(a0, a1); add2(a2, a3); add2(a0, a2);
        float lo, hi; unpack2(a0, lo, hi);
        const float dot = lo + hi;
        const int np = p ^ 1;

        if (isG) {
            const float gn = dot + pc;
            sbuf[np][tid] = gn;
            g_G[(size_t)(b + 1) * SD + tid] = gn;
        }
        if (w3) {
            // warp-local h chain: group0 lanes 8-15, group1 16-23, group2 24-31
            float acc = dot + pc;
            float val0 = tanh_hw(acc);                       // h_{3b+3} on group0
#pragma unroll
            for (int j = 0; j < 8; j++) {
                float h3j = __shfl_sync(0xffffffffu, val0, 8 + j);
                acc = fmaf(cpA[j], h3j, acc);
            }
            float val1 = tanh_hw(acc);                       // h_{3b+4} on group1
#pragma unroll
            for (int j = 0; j < 8; j++) {
                float h4j = __shfl_sync(0xffffffffu, val1, 16 + j);
                acc = fmaf(cpB[j], h4j, acc);
            }
            float val2 = tanh_hw(acc);                       // final per-lane h value
            if (tid >= 104) {
                const int c = tid - 104;                     // 0..23
                sbuf[np][100 + c] = val2;
                g_h[(size_t)(3 * b + 3 + (c >> 3)) * HID + (c & 7)] = val2;
            }
        }
        pc = pn; pn = pn2;
        __syncthreads();
        p = np;
    }
}

// ============================================================================
// 4) post: c_t reconstruction (3 rows per m) + y, GQ m's per CTA
// ============================================================================
__global__ void __launch_bounds__(128, 1) post_kernel(
    const float* __restrict__ w, const float* __restrict__ u,
    const float* __restrict__ Bw, const float* __restrict__ W2,
    const float* __restrict__ b2, const int* __restrict__ obs,
    float* __restrict__ outc, float* __restrict__ outy)
{
    __shared__ __align__(16) float4 at4s[SD * 25];
    __shared__ __align__(16) float va[SD];
    __shared__ float hh[32];
    __shared__ int obsS[NOBS];

    const int tid = threadIdx.x;
    const float4* gAt4 = reinterpret_cast<const float4*>(g_At4);
    for (int o = tid; o < SD * 25; o += 128) at4s[o] = gAt4[o];
    if (tid < NOBS) obsS[tid] = obs[tid];

    float bwx = 0.f, bwy = 0.f, db2 = 0.f, w2r[HID];
#pragma unroll
    for (int z = 0; z < HID; z++) w2r[z] = 0.f;
    if (tid < SD) {
        bwx = Bw[tid * 2]; bwy = Bw[tid * 2 + 1]; db2 = DTC * b2[tid];
#pragma unroll
        for (int z = 0; z < HID; z++) w2r[z] = DTC * W2[tid * HID + z];
    }
    __syncthreads();

    const float4* va4 = reinterpret_cast<const float4*>(va);

    for (int gi = 0; gi < GQ; gi++) {
        const int m = blockIdx.x * GQ + gi;
        const bool act = (m < NP);
        const int mc = act ? m : (NP - 1);
        const int t0 = 3 * mc;

        if (tid < 32) {
            int row = t0 + (tid >> 3);
            if (row > TT + 1) row = TT + 1;
            hh[tid] = g_h[(size_t)row * HID + (tid & 7)];
        }
        __syncthreads();
        if (tid < SD) {
            float s = g_G[(size_t)mc * SD + tid];
#pragma unroll
            for (int z = 0; z < HID; z++) s += w2r[z] * hh[z];
            va[tid] = s;                  // c_{3m}  (g_G[0]=c0, h_0=0 -> c_0 = c0)
        }
        __syncthreads();
#pragma unroll
        for (int s = 1; s <= 3; s++) {
            const int t = t0 + s;
            const bool vt = act && (t <= TT);
            const int tl = vt ? t : TT;   // clamp for safe loads
            float cv = 0.f;
            if (tid < SD) {
                cv = matvec100(at4s, va4, tid)
                   + bwx * w[2 * (tl - 1)] + bwy * w[2 * (tl - 1) + 1]
                   + u[(size_t)(tl - 1) * SD + tid] + db2;
#pragma unroll
                for (int z = 0; z < HID; z++) cv += w2r[z] * hh[8 * s + z];
            }
            __syncthreads();
            if (tid < SD) {
                va[tid] = cv;
                if (vt) outc[(size_t)(t - 1) * SD + tid] = cv;
            }
            __syncthreads();
            if (vt && tid < NOBS) outy[(size_t)(t - 1) * NOBS + tid] = va[obsS[tid]];
        }
        __syncthreads();
    }
}

extern "C" void kernel_launch(void* const* d_in, const int* in_sizes, int n_in,
                              void* d_out, int out_size) {
    const float* c0  = (const float*)d_in[0];
    const float* w   = (const float*)d_in[1];
    const float* u   = (const float*)d_in[2];
    const float* A   = (const float*)d_in[3];
    const float* Bw  = (const float*)d_in[4];
    const float* W1  = (const float*)d_in[5];
    const float* b1  = (const float*)d_in[6];
    const float* W2  = (const float*)d_in[7];
    const float* b2  = (const float*)d_in[8];
    const int*   ob  = (const int*)d_in[9];

    float* outc = (float*)d_out;                      // (T, 100)
    float* outy = (float*)d_out + (size_t)TT * SD;    // (T, 12)

    setup_kernel<<<1, 128>>>(A, Bw, W1, b1, W2, b2, c0, w, u);
    precomp_kernel<<<PRE_CTAS, 128>>>(w, u, Bw, W1, b1, b2);
    serial_kernel<<<1, 128>>>(c0);
    post_kernel<<<POST_CTAS, 128>>>(w, u, Bw, W2, b2, ob, outc, outy);
}

// round 7
// speedup vs baseline: 5.5626x; 5.5626x over previous
#include <cuda_runtime.h>

#define TT    65536
#define NB3   21845          /* 3*NB3 = 65535 serial 3-step blocks */
#define NP    21846          /* post blocks */
#define SD    100
#define HID   8
#define NOBS  12
#define DTC   0.01f
#define GQ    8
#define PRE_CTAS  ((NB3 + GQ - 1) / GQ)
#define POST_CTAS ((NP  + GQ - 1) / GQ)

__device__ __forceinline__ unsigned long long pack2(float lo, float hi) {
    unsigned long long r;
    asm("mov.b64 %0, {%1, %2};" : "=l"(r) : "f"(lo), "f"(hi));
    return r;
}
__device__ __forceinline__ void unpack2(unsigned long long v, float& lo, float& hi) {
    asm("mov.b64 {%0, %1}, %2;" : "=f"(lo), "=f"(hi) : "l"(v));
}
__device__ __forceinline__ void fma2(unsigned long long& acc, unsigned long long a, unsigned long long b) {
    asm("fma.rn.f32x2 %0, %1, %2, %0;" : "+l"(acc) : "l"(a), "l"(b));
}
__device__ __forceinline__ void add2(unsigned long long& acc, unsigned long long b) {
    asm("add.rn.f32x2 %0, %0, %1;" : "+l"(acc) : "l"(b));
}
__device__ __forceinline__ float tanh_hw(float x) {
    float r;
    asm("tanh.approx.f32 %0, %1;" : "=f"(r) : "f"(x));
    return r;
}

// ------------------------- device scratch -------------------------
__device__ float g_R[128 * 124];         // per-lane composite rows for serial dot
__device__ float g_At4[SD * SD];         // A in float4-interleaved matvec layout
__device__ float g_A2[SD * SD];          // A^2 (setup temp)
__device__ float g_U1[SD * HID];         // dt A W2
__device__ float g_U2[SD * HID];         // dt A^2 W2
__device__ float g_V0[64];               // dt W1 W2
__device__ float g_V1[64];               // dt W1 A W2
__device__ float g_P3[(size_t)NB3 * SD];
__device__ float g_Qq[(size_t)NB3 * 24]; // q0|q1|q2 per block
__device__ float g_G[(size_t)(NB3 + 1) * SD];   // g_{3b}
__device__ float g_h[(size_t)(TT + 2) * HID];   // h_t rows 0..65537

// ============================================================================
// 1) setup (1 CTA): composite matrices, At4 layout, h1/h2, initial rows
// ============================================================================
__global__ void __launch_bounds__(128, 1) setup_kernel(
    const float* __restrict__ A,  const float* __restrict__ Bw,
    const float* __restrict__ W1, const float* __restrict__ b1,
    const float* __restrict__ W2, const float* __restrict__ b2,
    const float* __restrict__ c0, const float* __restrict__ w,
    const float* __restrict__ u)
{
    __shared__ float As[SD * SD];     // 40000 B
    __shared__ float W2d[SD * HID];   // dt*W2
    __shared__ float W1s[SD * HID];   // W1, later U1, later U2 (staging reuse)
    __shared__ float cA[SD];
    __shared__ float cB[SD];
    __shared__ float h1s[HID];

    const int tid = threadIdx.x;

    // P0: stage inputs, init rows
    for (int i = tid; i < SD * SD; i += 128) As[i] = A[i];
    for (int i = tid; i < SD * HID; i += 128) W2d[i] = DTC * W2[i];
    for (int i = tid; i < SD * HID; i += 128) W1s[i] = W1[i];   // W1 is 8x100 = 800
    if (tid < SD) { cA[tid] = c0[tid]; g_G[tid] = c0[tid]; }
    if (tid < HID) g_h[tid] = 0.f;                              // h_0 = 0
    for (int o = tid; o < 4 * 124; o += 128) g_R[100 * 124 + o] = 0.f; // rows 100-103
    __syncthreads();
    for (int o = tid; o < SD * SD; o += 128) {
        int j4 = o / 400, rem = o % 400, i = rem / 4, r = rem % 4;
        g_At4[o] = As[i * SD + 4 * j4 + r];
    }

    // P0.5: cB = A c0 + IN_0 (no h term yet);  h1 = tanh(W1 c0 + b1)
    if (tid < SD) {
        const int i = tid;
        float s = Bw[i * 2] * w[0] + Bw[i * 2 + 1] * w[1] + u[i] + DTC * b2[i];
        for (int j = 0; j < SD; j++) s += As[i * SD + j] * cA[j];
        cB[i] = s;
    } else if (tid >= 104 && tid < 112) {
        const int z = tid - 104;
        float s = b1[z];
        for (int k = 0; k < SD; k++) s += W1s[z * SD + k] * cA[k];
        float h1 = tanh_hw(s);
        h1s[z] = h1;
        g_h[HID + z] = h1;
    }
    __syncthreads();
    // P0.6: cB += dtW2 h1  (now cB = c_1)
    if (tid < SD) {
        float s = cB[tid];
#pragma unroll
        for (int z = 0; z < HID; z++) s += W2d[tid * HID + z] * h1s[z];
        cB[tid] = s;
    }
    __syncthreads();
    // P0.7: h2 = tanh(W1 c1 + b1)
    if (tid >= 104 && tid < 112) {
        const int z = tid - 104;
        float s = b1[z];
        for (int k = 0; k < SD; k++) s += W1s[z * SD + k] * cB[k];
        g_h[2 * HID + z] = tanh_hw(s);
    }
    __syncthreads();

    // persistent per-lane arrays across phases
    float accA2[SD];
    float u1r[HID], u2r[HID];
    float wa[SD], wb[SD];
    float v0r[HID], v1r[HID], v2r[HID], v3r[HID], v4r[HID];

    // P1: A^2 rows + U1 (g lanes);  W1A + V0 (h lanes)
    if (tid < SD) {
        const int i = tid;
#pragma unroll
        for (int jj = 0; jj < SD; jj++) accA2[jj] = 0.f;
#pragma unroll
        for (int z = 0; z < HID; z++) u1r[z] = 0.f;
        for (int j = 0; j < SD; j++) {
            const float a = As[i * SD + j];
#pragma unroll
            for (int jj = 0; jj < SD; jj++) accA2[jj] += a * As[j * SD + jj];
#pragma unroll
            for (int z = 0; z < HID; z++) u1r[z] += a * W2d[j * HID + z];
        }
        for (int jj = 0; jj < SD; jj++) g_A2[i * SD + jj] = accA2[jj];
#pragma unroll
        for (int z = 0; z < HID; z++) g_U1[i * HID + z] = u1r[z];
    } else if (tid >= 104 && tid < 112) {
        const int z = tid - 104;
#pragma unroll
        for (int jj = 0; jj < SD; jj++) wa[jj] = 0.f;
#pragma unroll
        for (int zz = 0; zz < HID; zz++) v0r[zz] = 0.f;
        for (int k = 0; k < SD; k++) {
            const float wv = W1s[z * SD + k];
#pragma unroll
            for (int jj = 0; jj < SD; jj++) wa[jj] += wv * As[k * SD + jj];
#pragma unroll
            for (int zz = 0; zz < HID; zz++) v0r[zz] += wv * W2d[k * HID + zz];
        }
#pragma unroll
        for (int zz = 0; zz < HID; zz++) g_V0[z * HID + zz] = v0r[zz];
    }
    __syncthreads();
    // stage U1 into W1s
    for (int o = tid; o < SD * HID; o += 128) W1s[o] = g_U1[o];
    __syncthreads();

    // P2: A^3 rows -> g_R[0..99];  U2 = A U1;  h lanes: V1, wb = W1A^2
    if (tid < SD) {
        const int i = tid;
        float acc3[SD];
#pragma unroll
        for (int jj = 0; jj < SD; jj++) acc3[jj] = 0.f;
#pragma unroll
        for (int z = 0; z < HID; z++) u2r[z] = 0.f;
        for (int j = 0; j < SD; j++) {
            const float a2 = accA2[j];
            const float a1 = As[i * SD + j];
#pragma unroll
            for (int jj = 0; jj < SD; jj++) acc3[jj] += a2 * As[j * SD + jj];
#pragma unroll
            for (int z = 0; z < HID; z++) u2r[z] += a1 * W1s[j * HID + z];
        }
        for (int jj = 0; jj < SD; jj++) g_R[i * 124 + jj] = acc3[jj];
#pragma unroll
        for (int z = 0; z < HID; z++) g_U2[i * HID + z] = u2r[z];
    } else if (tid >= 104 && tid < 112) {
        const int z = tid - 104;
#pragma unroll
        for (int jj = 0; jj < SD; jj++) wb[jj] = 0.f;
#pragma unroll
        for (int zz = 0; zz < HID; zz++) v1r[zz] = 0.f;
        for (int k = 0; k < SD; k++) {
            const float wv = wa[k];
#pragma unroll
            for (int jj = 0; jj < SD; jj++) wb[jj] += wv * As[k * SD + jj];   // wb = W1A^2
#pragma unroll
            for (int zz = 0; zz < HID; zz++) v1r[zz] += wv * W2d[k * HID + zz];
        }
#pragma unroll
        for (int zz = 0; zz < HID; zz++) g_V1[z * HID + zz] = v1r[zz];
    }
    __syncthreads();
    // stage U2 into W1s
    for (int o = tid; o < SD * HID; o += 128) W1s[o] = g_U2[o];
    __syncthreads();

    // P3: U3 = A U2; assemble g rows tail.  h lanes: V2, wa3, V3, wa4, V4 + rows.
    if (tid < SD) {
        const int i = tid;
        float u3r[HID];
#pragma unroll
        for (int z = 0; z < HID; z++) u3r[z] = 0.f;
        for (int j = 0; j < SD; j++) {
            const float a1 = As[i * SD + j];
#pragma unroll
            for (int z = 0; z < HID; z++) u3r[z] += a1 * W1s[j * HID + z];
        }
#pragma unroll
        for (int z = 0; z < HID; z++) {
            g_R[i * 124 + 100 + z] = u3r[z];
            g_R[i * 124 + 108 + z] = u2r[z];
            g_R[i * 124 + 116 + z] = u1r[z];
        }
    } else if (tid >= 104 && tid < 112) {
        const int z = tid - 104;
#pragma unroll
        for (int zz = 0; zz < HID; zz++) v2r[zz] = 0.f;
        for (int k = 0; k < SD; k++) {
            const float wv = wb[k];
#pragma unroll
            for (int zz = 0; zz < HID; zz++) v2r[zz] += wv * W2d[k * HID + zz];
        }
        float wa3[SD];
#pragma unroll
        for (int jj = 0; jj < SD; jj++) wa3[jj] = 0.f;
        for (int k = 0; k < SD; k++) {
            const float wv = wb[k];
#pragma unroll
            for (int jj = 0; jj < SD; jj++) wa3[jj] += wv * As[k * SD + jj];
        }
#pragma unroll
        for (int zz = 0; zz < HID; zz++) v3r[zz] = 0.f;
        float wa4[SD];
#pragma unroll
        for (int jj = 0; jj < SD; jj++) wa4[jj] = 0.f;
        for (int k = 0; k < SD; k++) {
            const float wv = wa3[k];
#pragma unroll
            for (int zz = 0; zz < HID; zz++) v3r[zz] += wv * W2d[k * HID + zz];
#pragma unroll
            for (int jj = 0; jj < SD; jj++) wa4[jj] += wv * As[k * SD + jj];
        }
#pragma unroll
        for (int zz = 0; zz < HID; zz++) v4r[zz] = 0.f;
        for (int k = 0; k < SD; k++) {
            const float wv = wa4[k];
#pragma unroll
            for (int zz = 0; zz < HID; zz++) v4r[zz] += wv * W2d[k * HID + zz];
        }
        // group0 row (tid 104+z): [W1A^2 | V2 | V1 | V0]
        float* r0 = g_R + (104 + z) * 124;
        for (int jj = 0; jj < SD; jj++) r0[jj] = wb[jj];
#pragma unroll
        for (int zz = 0; zz < HID; zz++) {
            r0[100 + zz] = v2r[zz]; r0[108 + zz] = v1r[zz]; r0[116 + zz] = v0r[zz];
        }
        // group1 row (112+z): [W1A^3 | V3 | V2 | V1]
        float* r1 = g_R + (112 + z) * 124;
        for (int jj = 0; jj < SD; jj++) r1[jj] = wa3[jj];
#pragma unroll
        for (int zz = 0; zz < HID; zz++) {
            r1[100 + zz] = v3r[zz]; r1[108 + zz] = v2r[zz]; r1[116 + zz] = v1r[zz];
        }
        // group2 row (120+z): [W1A^4 | V4 | V3 | V2]
        float* r2 = g_R + (120 + z) * 124;
        for (int jj = 0; jj < SD; jj++) r2[jj] = wa4[jj];
#pragma unroll
        for (int zz = 0; zz < HID; zz++) {
            r2[100 + zz] = v4r[zz]; r2[108 + zz] = v3r[zz]; r2[116 + zz] = v2r[zz];
        }
    }
}

// float4 matvec: out_i = sum_j A[i][j] v[j]
__device__ __forceinline__ float matvec100(const float4* at4s, const float4* v4, int i) {
    float acc = 0.f;
#pragma unroll
    for (int j4 = 0; j4 < 25; j4++) {
        float4 m = at4s[j4 * SD + i];
        float4 x = v4[j4];
        acc = fmaf(m.x, x.x, acc); acc = fmaf(m.y, x.y, acc);
        acc = fmaf(m.z, x.z, acc); acc = fmaf(m.w, x.w, acc);
    }
    return acc;
}

// ============================================================================
// 2) precomp: P_b, q0_b, q1_b, q2_b — GQ blocks per CTA, A staged once
// ============================================================================
__global__ void __launch_bounds__(128, 1) precomp_kernel(
    const float* __restrict__ w, const float* __restrict__ u,
    const float* __restrict__ Bw, const float* __restrict__ W1,
    const float* __restrict__ b1, const float* __restrict__ b2)
{
    __shared__ __align__(16) float4 at4s[SD * 25];
    __shared__ float W1sm[SD * HID];
    __shared__ __align__(16) float va[SD];
    __shared__ __align__(16) float vb[SD];

    const int tid = threadIdx.x;
    const float4* gAt4 = reinterpret_cast<const float4*>(g_At4);
    for (int o = tid; o < SD * 25; o += 128) at4s[o] = gAt4[o];
    for (int o = tid; o < SD * HID; o += 128) W1sm[o] = W1[o];

    float bwx = 0.f, bwy = 0.f, db2 = 0.f;
    if (tid < SD) { bwx = Bw[tid * 2]; bwy = Bw[tid * 2 + 1]; db2 = DTC * b2[tid]; }
    float b1z = 0.f;
    if (tid >= 104 && tid < 112) b1z = b1[tid - 104];
    __syncthreads();

    const float4* va4 = reinterpret_cast<const float4*>(va);
    const float4* vb4 = reinterpret_cast<const float4*>(vb);

    for (int gi = 0; gi < GQ; gi++) {
        const int b = blockIdx.x * GQ + gi;
        const bool act = (b < NB3);
        const int bc = act ? b : (NB3 - 1);
        const size_t k = 3 * (size_t)bc;

        // va = IN_k
        if (tid < SD)
            va[tid] = bwx * w[2 * k] + bwy * w[2 * k + 1] + u[k * SD + tid] + db2;
        __syncthreads();
        // vb = A va + IN_{k+1}
        if (tid < SD)
            vb[tid] = matvec100(at4s, va4, tid)
                    + bwx * w[2 * k + 2] + bwy * w[2 * k + 3] + u[(k + 1) * SD + tid] + db2;
        __syncthreads();
        // vc = A vb + IN_{k+2} (= P);  q0 = W1 vb + b1
        float vcv = 0.f;
        if (tid < SD)
            vcv = matvec100(at4s, vb4, tid)
                + bwx * w[2 * k + 4] + bwy * w[2 * k + 5] + u[(k + 2) * SD + tid] + db2;
        else if (tid >= 104 && tid < 112) {
            const int z = tid - 104;
            float s = b1z;
#pragma unroll 4
            for (int j = 0; j < SD; j++) s += W1sm[z * SD + j] * vb[j];
            if (act) g_Qq[(size_t)b * 24 + z] = s;
        }
        __syncthreads();
        if (tid < SD) {
            va[tid] = vcv;
            if (act) g_P3[(size_t)b * SD + tid] = vcv;
        }
        __syncthreads();
        // vd = A P + IN_{k+3};  q1 = W1 P + b1
        float vdv = 0.f;
        if (tid < SD)
            vdv = matvec100(at4s, va4, tid)
                + bwx * w[2 * k + 6] + bwy * w[2 * k + 7] + u[(k + 3) * SD + tid] + db2;
        else if (tid >= 104 && tid < 112) {
            const int z = tid - 104;
            float s = b1z;
#pragma unroll 4
            for (int j = 0; j < SD; j++) s += W1sm[z * SD + j] * va[j];
            if (act) g_Qq[(size_t)b * 24 + 8 + z] = s;
        }
        __syncthreads();
        if (tid < SD) vb[tid] = vdv;
        __syncthreads();
        // q2 = W1 vd + b1
        if (tid >= 104 && tid < 112) {
            const int z = tid - 104;
            float s = b1z;
#pragma unroll 4
            for (int j = 0; j < SD; j++) s += W1sm[z * SD + j] * vb[j];
            if (act) g_Qq[(size_t)b * 24 + 16 + z] = s;
        }
        __syncthreads();
    }
}

// ============================================================================
// 3) serial: 21845 blocks of 3 steps, 1 CTA x 128 threads, ONE barrier/block.
//    Low register pressure: coupling coeffs in SMEM (volatile LDS in-chain),
//    pointer increments instead of index multiplies. Row regs = 62 ULL (as R3).
// ============================================================================
__global__ void __launch_bounds__(128, 1) serial_kernel(const float* __restrict__ c0)
{
    __shared__ __align__(16) float sbuf[2][128];
    __shared__ float sCpA[8][32];   // [j][lane]: h3-coupling coeff
    __shared__ float sCpB[8][32];   // [j][lane]: h4-coupling coeff

    const int tid = threadIdx.x;
    const bool isG = (tid < SD);
    const bool isH = (tid >= 104);   // chain lanes 8..31 of warp 3

    // init coupling smem: lane l = tid-96 (0..31)
    // l in [16,24): cpA = V0[l-16][j]          (group1)
    // l in [24,32): cpA = V1[l-24][j], cpB = V0[l-24][j]   (group2)
    for (int o = tid; o < 256; o += 128) {
        const int j = o >> 5, l = o & 31;
        float a = 0.f, bv = 0.f;
        if (l >= 16 && l < 24) a = g_V0[(l - 16) * 8 + j];
        else if (l >= 24) { a = g_V1[(l - 24) * 8 + j]; bv = g_V0[(l - 24) * 8 + j]; }
        sCpA[j][l] = a;
        sCpB[j][l] = bv;
    }

    // init S_0 = [c0 | h0=0 | h1 | h2]
    if (tid < SD)       sbuf[0][tid] = c0[tid];
    else if (tid < 108) sbuf[0][tid] = 0.f;
    else if (tid < 116) sbuf[0][tid] = g_h[HID + (tid - 108)];
    else if (tid < 124) sbuf[0][tid] = g_h[2 * HID + (tid - 116)];
    else                sbuf[0][tid] = 0.f;
    sbuf[1][tid] = 0.f;

    // composite row: exactly 62 ULL = 124 regs (same as R3's proven-fitting layout)
    unsigned long long rva[62];
    {
        const float* Rr = g_R + tid * 124;
#pragma unroll
        for (int q = 0; q < 62; q++) rva[q] = pack2(Rr[2 * q], Rr[2 * q + 1]);
    }

    // smem addresses for in-chain coefficient loads
    const int l = tid & 31;  // lane (warp3: tid-96)
    const unsigned aA = (unsigned)__cvta_generic_to_shared(&sCpA[0][l]);
    const unsigned aB = (unsigned)__cvta_generic_to_shared(&sCpB[0][l]);

    __syncthreads();

    // depth-2 prefetch pointers (advance by constant; clamp near tail)
    const float* pPtr = 0;
    float pc = 0.f, pn = 0.f;
    if (isG) {
        pc = g_P3[tid]; pn = g_P3[SD + tid];
        pPtr = g_P3 + 2 * SD + tid;
    } else if (isH) {
        pc = g_Qq[tid - 104]; pn = g_Qq[24 + (tid - 104)];
        pPtr = g_Qq + 2 * 24 + (tid - 104);
    }
    // output pointers
    float* gPtr = g_G + SD + tid;                                  // g_{b+1} row
    float* hPtr = 0;
    if (isH) {
        const int c = tid - 104;                                   // 0..23
        hPtr = g_h + (size_t)(3 + (c >> 3)) * HID + (c & 7);
    }

    int p = 0;
    for (int b = 0; b < NB3; b++) {
        float pn2 = 0.f;
        if (pPtr) pn2 = __ldcg(pPtr);

        // 124-long dot vs S_b
        unsigned long long a0 = 0ull, a1 = 0ull, a2 = 0ull, a3 = 0ull;
        const ulonglong2* sp = reinterpret_cast<const ulonglong2*>(sbuf[p]);
#pragma unroll
        for (int q = 0; q < 31; q++) {
            ulonglong2 gg = sp[q];
            if (q & 1) { fma2(a2, rva[2 * q], gg.x); fma2(a3, rva[2 * q + 1], gg.y); }
            else       { fma2(a0, rva[2 * q], gg.x); fma2(a1, rva[2 * q + 1], gg.y); }
        }
        add2(a0, a1); add2(a2, a3); add2(a0, a2);
        float lo, hi; unpack2(a0, lo, hi);
        const float dot = lo + hi;
        const int np = p ^ 1;

        if (isG) {
            const float gn = dot + pc;
            sbuf[np][tid] = gn;
            *gPtr = gn;
            gPtr += SD;
        }
        if (isH) {
            // warp-local h chain (lanes 8..31), coeffs via volatile LDS
            float acc = dot + pc;
            float val0 = tanh_hw(acc);
            float ca[8], cb[8];
#pragma unroll
            for (int j = 0; j < 8; j++) {
                asm volatile("ld.shared.f32 %0, [%1];" : "=f"(ca[j]) : "r"(aA + j * 128));
                asm volatile("ld.shared.f32 %0, [%1];" : "=f"(cb[j]) : "r"(aB + j * 128));
            }
#pragma unroll
            for (int j = 0; j < 8; j++) {
                float h3j = __shfl_sync(0xFFFFFF00u, val0, 8 + j);
                acc = fmaf(ca[j], h3j, acc);
            }
            float val1 = tanh_hw(acc);
#pragma unroll
            for (int j = 0; j < 8; j++) {
                float h4j = __shfl_sync(0xFFFFFF00u, val1, 16 + j);
                acc = fmaf(cb[j], h4j, acc);
            }
            float val2 = tanh_hw(acc);
            sbuf[np][100 + (tid - 104)] = val2;
            *hPtr = val2;
            hPtr += 24;
        }
        pc = pn; pn = pn2;
        if (b < NB3 - 3 && pPtr) pPtr += (isG ? SD : 24);
        __syncthreads();
        p = np;
    }
}

// ============================================================================
// 4) post: c_t reconstruction (3 rows per m) + y, GQ m's per CTA
// ============================================================================
__global__ void __launch_bounds__(128, 1) post_kernel(
    const float* __restrict__ w, const float* __restrict__ u,
    const float* __restrict__ Bw, const float* __restrict__ W2,
    const float* __restrict__ b2, const int* __restrict__ obs,
    float* __restrict__ outc, float* __restrict__ outy)
{
    __shared__ __align__(16) float4 at4s[SD * 25];
    __shared__ __align__(16) float va[SD];
    __shared__ float hh[32];
    __shared__ int obsS[NOBS];

    const int tid = threadIdx.x;
    const float4* gAt4 = reinterpret_cast<const float4*>(g_At4);
    for (int o = tid; o < SD * 25; o += 128) at4s[o] = gAt4[o];
    if (tid < NOBS) obsS[tid] = obs[tid];

    float bwx = 0.f, bwy = 0.f, db2 = 0.f, w2r[HID];
#pragma unroll
    for (int z = 0; z < HID; z++) w2r[z] = 0.f;
    if (tid < SD) {
        bwx = Bw[tid * 2]; bwy = Bw[tid * 2 + 1]; db2 = DTC * b2[tid];
#pragma unroll
        for (int z = 0; z < HID; z++) w2r[z] = DTC * W2[tid * HID + z];
    }
    __syncthreads();

    const float4* va4 = reinterpret_cast<const float4*>(va);

    for (int gi = 0; gi < GQ; gi++) {
        const int m = blockIdx.x * GQ + gi;
        const bool act = (m < NP);
        const int mc = act ? m : (NP - 1);
        const int t0 = 3 * mc;

        if (tid < 32) {
            int row = t0 + (tid >> 3);
            if (row > TT + 1) row = TT + 1;
            hh[tid] = g_h[(size_t)row * HID + (tid & 7)];
        }
        __syncthreads();
        if (tid < SD) {
            float s = g_G[(size_t)mc * SD + tid];
#pragma unroll
            for (int z = 0; z < HID; z++) s += w2r[z] * hh[z];
            va[tid] = s;                  // c_{3m}
        }
        __syncthreads();
#pragma unroll
        for (int s = 1; s <= 3; s++) {
            const int t = t0 + s;
            const bool vt = act && (t <= TT);
            const int tl = vt ? t : TT;
            float cv = 0.f;
            if (tid < SD) {
                cv = matvec100(at4s, va4, tid)
                   + bwx * w[2 * (tl - 1)] + bwy * w[2 * (tl - 1) + 1]
                   + u[(size_t)(tl - 1) * SD + tid] + db2;
#pragma unroll
                for (int z = 0; z < HID; z++) cv += w2r[z] * hh[8 * s + z];
            }
            __syncthreads();
            if (tid < SD) {
                va[tid] = cv;
                if (vt) outc[(size_t)(t - 1) * SD + tid] = cv;
            }
            __syncthreads();
            if (vt && tid < NOBS) outy[(size_t)(t - 1) * NOBS + tid] = va[obsS[tid]];
        }
        __syncthreads();
    }
}

extern "C" void kernel_launch(void* const* d_in, const int* in_sizes, int n_in,
                              void* d_out, int out_size) {
    const float* c0  = (const float*)d_in[0];
    const float* w   = (const float*)d_in[1];
    const float* u   = (const float*)d_in[2];
    const float* A   = (const float*)d_in[3];
    const float* Bw  = (const float*)d_in[4];
    const float* W1  = (const float*)d_in[5];
    const float* b1  = (const float*)d_in[6];
    const float* W2  = (const float*)d_in[7];
    const float* b2  = (const float*)d_in[8];
    const int*   ob  = (const int*)d_in[9];

    float* outc = (float*)d_out;                      // (T, 100)
    float* outy = (float*)d_out + (size_t)TT * SD;    // (T, 12)

    setup_kernel<<<1, 128>>>(A, Bw, W1, b1, W2, b2, c0, w, u);
    precomp_kernel<<<PRE_CTAS, 128>>>(w, u, Bw, W1, b1, b2);
    serial_kernel<<<1, 128>>>(c0);
    post_kernel<<<POST_CTAS, 128>>>(w, u, Bw, W2, b2, ob, outc, outy);
}

// round 8
// speedup vs baseline: 7.0376x; 1.2652x over previous
#include <cuda_runtime.h>

#define TT    65536
#define NB4   16384          /* 4*NB4 = 65536 serial 4-step blocks */
#define SD    100
#define HID   8
#define NOBS  12
#define DTC   0.01f
#define SW    132            /* state width */
#define GQ    8
#define PRE_CTAS  (NB4 / GQ) /* 2048, exact */
#define POST_CTAS (NB4 / GQ) /* 2048, exact */

__device__ __forceinline__ unsigned long long pack2(float lo, float hi) {
    unsigned long long r;
    asm("mov.b64 %0, {%1, %2};" : "=l"(r) : "f"(lo), "f"(hi));
    return r;
}
__device__ __forceinline__ void unpack2(unsigned long long v, float& lo, float& hi) {
    asm("mov.b64 {%0, %1}, %2;" : "=f"(lo), "=f"(hi) : "l"(v));
}
__device__ __forceinline__ void fma2(unsigned long long& acc, unsigned long long a, unsigned long long b) {
    asm("fma.rn.f32x2 %0, %1, %2, %0;" : "+l"(acc) : "l"(a), "l"(b));
}
__device__ __forceinline__ void add2(unsigned long long& acc, unsigned long long b) {
    asm("add.rn.f32x2 %0, %0, %1;" : "+l"(acc) : "l"(b));
}
__device__ __forceinline__ float tanh_hw(float x) {
    float r;
    asm("tanh.approx.f32 %0, %1;" : "=f"(r) : "f"(x));
    return r;
}

// ------------------------- device scratch -------------------------
__device__ float g_R[132 * SW];          // rows 0-99: c-rows; 100-131: chain rows
__device__ float g_At4[SD * SD];         // A in float4-interleaved matvec layout
__device__ float g_U1[SD * HID];         // dt A W2
__device__ float g_U2[SD * HID];         // dt A^2 W2
__device__ float g_V[7 * 64];            // V_j = dt W1 A^j W2, j=0..6
__device__ float g_P4[(size_t)NB4 * SD];
__device__ float g_Qq[(size_t)NB4 * 32]; // q0|q1|q2|q3 per block
__device__ float g_G[(size_t)(NB4 + 1) * SD];   // anchors c_{4b} (row 0 = c0)
__device__ float g_h[(size_t)(TT + 9) * HID];   // h_t rows

// ============================================================================
// 1a) setup1 (1 CTA): c-rows [A^4 | dtA^3W2 | dtA^2W2 | dtAW2 | dtW2],
//     At4 layout, initial rollout h1..h4, anchor row 0.
// ============================================================================
__global__ void __launch_bounds__(128, 1) setup1_kernel(
    const float* __restrict__ A,  const float* __restrict__ Bw,
    const float* __restrict__ W1, const float* __restrict__ b1,
    const float* __restrict__ W2, const float* __restrict__ b2,
    const float* __restrict__ c0, const float* __restrict__ w,
    const float* __restrict__ u)
{
    __shared__ float As[SD * SD];     // 40000 B
    __shared__ float W2d[SD * HID];   // dt*W2
    __shared__ float W1s[SD * HID];   // W1 -> U1 -> U2 staging
    __shared__ float cva[SD];
    __shared__ float cvb[SD];
    __shared__ float hh[HID];

    const int tid = threadIdx.x;

    for (int i = tid; i < SD * SD; i += 128) As[i] = A[i];
    for (int i = tid; i < SD * HID; i += 128) W2d[i] = DTC * W2[i];
    for (int i = tid; i < SD * HID; i += 128) W1s[i] = W1[i];
    if (tid < SD) { cva[tid] = c0[tid]; g_G[tid] = c0[tid]; }
    __syncthreads();
    for (int o = tid; o < SD * SD; o += 128) {
        int j4 = o / 400, rem = o % 400, i = rem / 4, r = rem % 4;
        g_At4[o] = As[i * SD + 4 * j4 + r];
    }

    // ---- initial rollout: h_t = tanh(W1 c_{t-1} + b1), c_t = A c_{t-1} + in_t + dtW2 h_t
    float* cc = cva; float* cn = cvb;
    for (int t = 1; t <= 4; t++) {
        if (tid >= 104 && tid < 112) {
            const int z = tid - 104;
            float s = b1[z];
            for (int k = 0; k < SD; k++) s += W1s[z * SD + k] * cc[k];
            float ht = tanh_hw(s);
            hh[z] = ht;
            g_h[(size_t)t * HID + z] = ht;
        }
        __syncthreads();
        if (t < 4 && tid < SD) {
            const int i = tid;
            float s = Bw[i * 2] * w[(t - 1) * 2] + Bw[i * 2 + 1] * w[(t - 1) * 2 + 1]
                    + u[(size_t)(t - 1) * SD + i] + DTC * b2[i];
            for (int j = 0; j < SD; j++) s += As[i * SD + j] * cc[j];
#pragma unroll
            for (int z = 0; z < HID; z++) s += W2d[i * HID + z] * hh[z];
            cn[i] = s;
        }
        __syncthreads();
        float* t2 = cc; cc = cn; cn = t2;
    }

    // ---- per-g-lane: A^2 -> A^3 -> A^4 rows; u1 = dtAW2 row
    float ra[SD], rb[SD];
    float u1r[HID], u2r[HID];
    if (tid < SD) {
        const int i = tid;
#pragma unroll
        for (int jj = 0; jj < SD; jj++) ra[jj] = 0.f;
#pragma unroll
        for (int z = 0; z < HID; z++) u1r[z] = 0.f;
        for (int j = 0; j < SD; j++) {
            const float a = As[i * SD + j];
#pragma unroll
            for (int jj = 0; jj < SD; jj++) ra[jj] += a * As[j * SD + jj];   // A^2 row
#pragma unroll
            for (int z = 0; z < HID; z++) u1r[z] += a * W2d[j * HID + z];
        }
#pragma unroll
        for (int z = 0; z < HID; z++) g_U1[i * HID + z] = u1r[z];
        // A^3
#pragma unroll
        for (int jj = 0; jj < SD; jj++) rb[jj] = 0.f;
        for (int j = 0; j < SD; j++) {
            const float a = ra[j];
#pragma unroll
            for (int jj = 0; jj < SD; jj++) rb[jj] += a * As[j * SD + jj];
        }
        // A^4 into ra
#pragma unroll
        for (int jj = 0; jj < SD; jj++) ra[jj] = 0.f;
        for (int j = 0; j < SD; j++) {
            const float a = rb[j];
#pragma unroll
            for (int jj = 0; jj < SD; jj++) ra[jj] += a * As[j * SD + jj];
        }
        for (int jj = 0; jj < SD; jj++) g_R[i * SW + jj] = ra[jj];
    }
    __syncthreads();
    for (int o = tid; o < SD * HID; o += 128) W1s[o] = g_U1[o];
    __syncthreads();
    // u2 = A U1 row
    if (tid < SD) {
        const int i = tid;
#pragma unroll
        for (int z = 0; z < HID; z++) u2r[z] = 0.f;
        for (int j = 0; j < SD; j++) {
            const float a = As[i * SD + j];
#pragma unroll
            for (int z = 0; z < HID; z++) u2r[z] += a * W1s[j * HID + z];
        }
#pragma unroll
        for (int z = 0; z < HID; z++) g_U2[i * HID + z] = u2r[z];
    }
    __syncthreads();
    for (int o = tid; o < SD * HID; o += 128) W1s[o] = g_U2[o];
    __syncthreads();
    // u3 = A U2 row; write tails [u3|u2|u1|u0]
    if (tid < SD) {
        const int i = tid;
        float u3r[HID];
#pragma unroll
        for (int z = 0; z < HID; z++) u3r[z] = 0.f;
        for (int j = 0; j < SD; j++) {
            const float a = As[i * SD + j];
#pragma unroll
            for (int z = 0; z < HID; z++) u3r[z] += a * W1s[j * HID + z];
        }
#pragma unroll
        for (int z = 0; z < HID; z++) {
            g_R[i * SW + 100 + z] = u3r[z];
            g_R[i * SW + 108 + z] = u2r[z];
            g_R[i * SW + 116 + z] = u1r[z];
            g_R[i * SW + 124 + z] = W2d[i * HID + z];   // u0 = dtW2 row
        }
    }
}

// ============================================================================
// 1b) setup2 (1 CTA): chain rows (W1A^{4+i} heads, V tails) + V tables.
//     Block-parallel W1 A^k chain via smem ping-pong.
// ============================================================================
__global__ void __launch_bounds__(128, 1) setup2_kernel(
    const float* __restrict__ A, const float* __restrict__ W1,
    const float* __restrict__ W2)
{
    __shared__ float As[SD * SD];
    __shared__ float bufA[SD * HID];
    __shared__ float bufB[SD * HID];

    const int tid = threadIdx.x;
    for (int i = tid; i < SD * SD; i += 128) As[i] = A[i];
    for (int i = tid; i < SD * HID; i += 128) bufA[i] = W1[i];   // cur = W1 (layout [z][j])
    __syncthreads();

    float* cur = bufA;
    float* nxt = bufB;

    // V0 = dt * W1 W2
    for (int o = tid; o < 64; o += 128) {
        const int z = o >> 3, zz = o & 7;
        float s = 0.f;
        for (int j = 0; j < SD; j++) s += cur[z * SD + j] * (DTC * W2[j * HID + zz]);
        g_V[o] = s;
    }
    __syncthreads();

    for (int k = 1; k <= 7; k++) {
        // nxt = cur * A
        for (int o = tid; o < SD * HID; o += 128) {
            const int z = o / SD, jj = o % SD;
            float s = 0.f;
            for (int j = 0; j < SD; j++) s += cur[z * SD + j] * As[j * SD + jj];
            nxt[o] = s;
        }
        __syncthreads();
        float* t = cur; cur = nxt; nxt = t;
        // heads for k >= 4: row 100 + 8*(k-4) + z
        if (k >= 4) {
            for (int o = tid; o < SD * HID; o += 128) {
                const int z = o / SD, jj = o % SD;
                g_R[(size_t)(100 + 8 * (k - 4) + z) * SW + jj] = cur[o];
            }
        }
        // V_k for k <= 6
        if (k <= 6) {
            for (int o = tid; o < 64; o += 128) {
                const int z = o >> 3, zz = o & 7;
                float s = 0.f;
                for (int j = 0; j < SD; j++) s += cur[z * SD + j] * (DTC * W2[j * HID + zz]);
                g_V[k * 64 + o] = s;
            }
        }
        __syncthreads();
    }

    // tails: row 100+l (l = 8i+z), col 100 + 8m + zz = V_{3+i-m}[z][zz]
    for (int o = tid; o < 32 * 32; o += 128) {
        const int l = o >> 5, cidx = o & 31;
        const int m = cidx >> 3, zz = cidx & 7;
        const int i = l >> 3, z = l & 7;
        const int d = 3 + i - m;   // 0..6
        g_R[(size_t)(100 + l) * SW + 100 + cidx] = g_V[d * 64 + z * HID + zz];
    }
}

// float4 matvec: out_i = sum_j A[i][j] v[j]
__device__ __forceinline__ float matvec100(const float4* at4s, const float4* v4, int i) {
    float acc = 0.f;
#pragma unroll
    for (int j4 = 0; j4 < 25; j4++) {
        float4 m = at4s[j4 * SD + i];
        float4 x = v4[j4];
        acc = fmaf(m.x, x.x, acc); acc = fmaf(m.y, x.y, acc);
        acc = fmaf(m.z, x.z, acc); acc = fmaf(m.w, x.w, acc);
    }
    return acc;
}

// ============================================================================
// 2) precomp: P_b (input composite for c_{4b+4}) and q0..q3 (for h_{4b+5..8})
// ============================================================================
__global__ void __launch_bounds__(128, 1) precomp_kernel(
    const float* __restrict__ w, const float* __restrict__ u,
    const float* __restrict__ Bw, const float* __restrict__ W1,
    const float* __restrict__ b1, const float* __restrict__ b2)
{
    __shared__ __align__(16) float4 at4s[SD * 25];
    __shared__ float W1sm[SD * HID];
    __shared__ __align__(16) float va[SD];
    __shared__ __align__(16) float vb[SD];

    const int tid = threadIdx.x;
    const float4* gAt4 = reinterpret_cast<const float4*>(g_At4);
    for (int o = tid; o < SD * 25; o += 128) at4s[o] = gAt4[o];
    for (int o = tid; o < SD * HID; o += 128) W1sm[o] = W1[o];

    float bwx = 0.f, bwy = 0.f, db2 = 0.f;
    if (tid < SD) { bwx = Bw[tid * 2]; bwy = Bw[tid * 2 + 1]; db2 = DTC * b2[tid]; }
    float b1z = 0.f;
    if (tid >= 104 && tid < 112) b1z = b1[tid - 104];
    __syncthreads();

    const float4* va4 = reinterpret_cast<const float4*>(va);
    const float4* vb4 = reinterpret_cast<const float4*>(vb);

    for (int gi = 0; gi < GQ; gi++) {
        const int b = blockIdx.x * GQ + gi;
        const size_t k = 4 * (size_t)b;

        // in_t helper via clamp: t <= TT
#define INW(t)  ((size_t)(((t) <= TT ? (t) : TT) - 1))
        // s0: va = in_{k+1}
        if (tid < SD)
            va[tid] = bwx * w[INW(k + 1) * 2] + bwy * w[INW(k + 1) * 2 + 1]
                    + u[INW(k + 1) * SD + tid] + db2;
        __syncthreads();
        // s1: vb = A va + in_{k+2}
        if (tid < SD)
            vb[tid] = matvec100(at4s, va4, tid)
                    + bwx * w[INW(k + 2) * 2] + bwy * w[INW(k + 2) * 2 + 1]
                    + u[INW(k + 2) * SD + tid] + db2;
        __syncthreads();
        // s2: va = A vb + in_{k+3}
        if (tid < SD)
            va[tid] = matvec100(at4s, vb4, tid)
                    + bwx * w[INW(k + 3) * 2] + bwy * w[INW(k + 3) * 2 + 1]
                    + u[INW(k + 3) * SD + tid] + db2;
        __syncthreads();
        // s3: vb = A va + in_{k+4}   (= P_b)
        if (tid < SD)
            vb[tid] = matvec100(at4s, va4, tid)
                    + bwx * w[INW(k + 4) * 2] + bwy * w[INW(k + 4) * 2 + 1]
                    + u[INW(k + 4) * SD + tid] + db2;
        __syncthreads();
        // s4: store P; va = A P + in_{k+5}; q0 = W1 P + b1
        if (tid < SD) {
            g_P4[(size_t)b * SD + tid] = vb[tid];
            va[tid] = matvec100(at4s, vb4, tid)
                    + bwx * w[INW(k + 5) * 2] + bwy * w[INW(k + 5) * 2 + 1]
                    + u[INW(k + 5) * SD + tid] + db2;
        } else if (tid >= 104 && tid < 112) {
            const int z = tid - 104;
            float s = b1z;
#pragma unroll 4
            for (int j = 0; j < SD; j++) s += W1sm[z * SD + j] * vb[j];
            g_Qq[(size_t)b * 32 + z] = s;
        }
        __syncthreads();
        // s5: vb = A va + in_{k+6}; q1 = W1 va + b1
        if (tid < SD)
            vb[tid] = matvec100(at4s, va4, tid)
                    + bwx * w[INW(k + 6) * 2] + bwy * w[INW(k + 6) * 2 + 1]
                    + u[INW(k + 6) * SD + tid] + db2;
        else if (tid >= 104 && tid < 112) {
            const int z = tid - 104;
            float s = b1z;
#pragma unroll 4
            for (int j = 0; j < SD; j++) s += W1sm[z * SD + j] * va[j];
            g_Qq[(size_t)b * 32 + 8 + z] = s;
        }
        __syncthreads();
        // s6: va = A vb + in_{k+7}; q2 = W1 vb + b1
        if (tid < SD)
            va[tid] = matvec100(at4s, vb4, tid)
                    + bwx * w[INW(k + 7) * 2] + bwy * w[INW(k + 7) * 2 + 1]
                    + u[INW(k + 7) * SD + tid] + db2;
        else if (tid >= 104 && tid < 112) {
            const int z = tid - 104;
            float s = b1z;
#pragma unroll 4
            for (int j = 0; j < SD; j++) s += W1sm[z * SD + j] * vb[j];
            g_Qq[(size_t)b * 32 + 16 + z] = s;
        }
        __syncthreads();
        // s7: q3 = W1 va + b1
        if (tid >= 104 && tid < 112) {
            const int z = tid - 104;
            float s = b1z;
#pragma unroll 4
            for (int j = 0; j < SD; j++) s += W1sm[z * SD + j] * va[j];
            g_Qq[(size_t)b * 32 + 24 + z] = s;
        }
        __syncthreads();
#undef INW
    }
}

// ============================================================================
// 3) serial: 16384 four-step blocks, 160 threads, ONE barrier/phase.
//    w0-2: c rows 0-95 (full 132-dot each). w3: chain (32 lanes, own SMSP).
//    w4: c rows 96-99, each split across 8 lanes + shfl_xor reduce.
// ============================================================================
__global__ void __launch_bounds__(160, 1) serial_kernel(const float* __restrict__ c0)
{
    __shared__ __align__(16) float sbuf[2][136];
    __shared__ float sC[3][8][32];

    const int tid = threadIdx.x;
    const int wid = tid >> 5;
    const int l   = tid & 31;
    const bool isG     = (wid < 3);
    const bool isChain = (wid == 3);
    const bool isW4    = (wid == 4);
    const int grp = l >> 3;          // w4: which of rows 96..99
    const int seg = l & 7;           // w4: segment
    const int ci  = l >> 3;          // chain group
    // sC tables: sC[s][j][lane] = V_{i-s-1}[z][j] (i>s), else 0
    for (int o = tid; o < 768; o += 160) {
        const int s = o >> 8, r = o & 255, j = r >> 5, lane = r & 31;
        const int i = lane >> 3, z = lane & 7;
        float v = 0.f;
        if (i > s) v = g_V[(i - s - 1) * 64 + z * HID + j];
        sC[s][j][lane] = v;
    }
    // init S_0 = [c0 | h1 | h2 | h3 | h4]
    if (tid < SD)        sbuf[0][tid] = c0[tid];
    else if (tid < SW)   sbuf[0][tid] = g_h[(size_t)(1 + ((tid - 100) >> 3)) * HID + ((tid - 100) & 7)];
    else if (tid < 136)  sbuf[0][tid] = 0.f;
    if (tid < 136) sbuf[1][tid] = 0.f;

    // rows
    unsigned long long rva[66];
    unsigned long long rw4[9];
    if (isG || isChain) {
        const float* Rr = g_R + (size_t)(isG ? tid : (100 + l)) * SW;
#pragma unroll
        for (int q = 0; q < 66; q++) rva[q] = pack2(Rr[2 * q], Rr[2 * q + 1]);
    } else {
        const float* Rr = g_R + (size_t)(96 + grp) * SW;
#pragma unroll
        for (int k = 0; k < 9; k++) {
            const int idx = seg + 8 * k;
            rw4[k] = (idx < 66) ? pack2(Rr[2 * idx], Rr[2 * idx + 1]) : 0ull;
        }
    }

    // in-chain coeff base addresses
    const unsigned aS = (unsigned)__cvta_generic_to_shared(&sC[0][0][l]);

    // prefetch (depth 2)
    const float* pPtr = 0;
    float pc = 0.f, pn = 0.f;
    if (isG) {
        pc = g_P4[tid]; pn = g_P4[SD + tid];
        pPtr = g_P4 + 2 * SD + tid;
    } else if (isChain) {
        pc = g_Qq[l]; pn = g_Qq[32 + l];
        pPtr = g_Qq + 2 * 32 + l;
    } else if (isW4 && seg == 0) {
        pc = g_P4[96 + grp]; pn = g_P4[SD + 96 + grp];
        pPtr = g_P4 + 2 * SD + 96 + grp;
    }
    float* gPtr = g_G + SD + (isG ? tid : (96 + grp));
    float* hPtr = g_h + (size_t)(5 + ci) * HID + (l & 7);

    __syncthreads();

    int p = 0;
    for (int b = 0; b < NB4; b++) {
        float pn2 = 0.f;
        if (pPtr) pn2 = __ldcg(pPtr);

        float dotv = 0.f;
        if (isG || isChain) {
            unsigned long long a0 = 0ull, a1 = 0ull, a2 = 0ull, a3 = 0ull;
            const ulonglong2* sp = reinterpret_cast<const ulonglong2*>(sbuf[p]);
#pragma unroll
            for (int q = 0; q < 33; q++) {
                ulonglong2 gg = sp[q];
                if (q & 1) { fma2(a2, rva[2 * q], gg.x); fma2(a3, rva[2 * q + 1], gg.y); }
                else       { fma2(a0, rva[2 * q], gg.x); fma2(a1, rva[2 * q + 1], gg.y); }
            }
            add2(a0, a1); add2(a2, a3); add2(a0, a2);
            float lo, hi; unpack2(a0, lo, hi);
            dotv = lo + hi;
        } else {
            // w4: split dot + butterfly reduce within 8-lane groups
            unsigned long long a0 = 0ull;
            const unsigned long long* sp = reinterpret_cast<const unsigned long long*>(sbuf[p]);
#pragma unroll
            for (int k = 0; k < 9; k++) {
                const int idx = seg + 8 * k;
                if (idx < 66) fma2(a0, rw4[k], sp[idx]);
            }
            float lo, hi; unpack2(a0, lo, hi);
            float v = lo + hi;
            v += __shfl_xor_sync(0xffffffffu, v, 1);
            v += __shfl_xor_sync(0xffffffffu, v, 2);
            v += __shfl_xor_sync(0xffffffffu, v, 4);
            dotv = v;
        }
        const int np = p ^ 1;

        if (isG) {
            const float gn = dotv + pc;
            sbuf[np][tid] = gn;
            *gPtr = gn; gPtr += SD;
        } else if (isW4) {
            if (seg == 0) {
                const float gn = dotv + pc;
                sbuf[np][96 + grp] = gn;
                *gPtr = gn;
            }
            gPtr += SD;
        } else {
            // chain: 3 coupling stages, all in warp 3
            float acc = dotv + pc;
            float val0 = tanh_hw(acc);
            float c[8];
#pragma unroll
            for (int j = 0; j < 8; j++)
                asm volatile("ld.shared.f32 %0, [%1];" : "=f"(c[j]) : "r"(aS + j * 128));
#pragma unroll
            for (int j = 0; j < 8; j++)
                acc = fmaf(c[j], __shfl_sync(0xffffffffu, val0, j), acc);
            float val1 = tanh_hw(acc);
#pragma unroll
            for (int j = 0; j < 8; j++)
                asm volatile("ld.shared.f32 %0, [%1];" : "=f"(c[j]) : "r"(aS + 1024 + j * 128));
#pragma unroll
            for (int j = 0; j < 8; j++)
                acc = fmaf(c[j], __shfl_sync(0xffffffffu, val1, 8 + j), acc);
            float val2 = tanh_hw(acc);
#pragma unroll
            for (int j = 0; j < 8; j++)
                asm volatile("ld.shared.f32 %0, [%1];" : "=f"(c[j]) : "r"(aS + 2048 + j * 128));
#pragma unroll
            for (int j = 0; j < 8; j++)
                acc = fmaf(c[j], __shfl_sync(0xffffffffu, val2, 16 + j), acc);
            float val3 = tanh_hw(acc);
            float hv = (l < 8) ? val0 : (l < 16) ? val1 : (l < 24) ? val2 : val3;
            sbuf[np][100 + l] = hv;
            *hPtr = hv; hPtr += 32;
        }

        pc = pn; pn = pn2;
        if (pPtr && b < NB4 - 3) pPtr += (isChain ? 32 : SD);
        __syncthreads();
        p = np;
    }
}

// ============================================================================
// 4) post: reconstruct c_{4m+1..3} from anchors + h; anchor m+1 row; y.
// ============================================================================
__global__ void __launch_bounds__(128, 1) post_kernel(
    const float* __restrict__ w, const float* __restrict__ u,
    const float* __restrict__ Bw, const float* __restrict__ W2,
    const float* __restrict__ b2, const int* __restrict__ obs,
    float* __restrict__ outc, float* __restrict__ outy)
{
    __shared__ __align__(16) float4 at4s[SD * 25];
    __shared__ __align__(16) float va[SD];
    __shared__ float hh[32];
    __shared__ int obsS[NOBS];

    const int tid = threadIdx.x;
    const float4* gAt4 = reinterpret_cast<const float4*>(g_At4);
    for (int o = tid; o < SD * 25; o += 128) at4s[o] = gAt4[o];
    if (tid < NOBS) obsS[tid] = obs[tid];

    float bwx = 0.f, bwy = 0.f, db2 = 0.f, w2r[HID];
#pragma unroll
    for (int z = 0; z < HID; z++) w2r[z] = 0.f;
    if (tid < SD) {
        bwx = Bw[tid * 2]; bwy = Bw[tid * 2 + 1]; db2 = DTC * b2[tid];
#pragma unroll
        for (int z = 0; z < HID; z++) w2r[z] = DTC * W2[tid * HID + z];
    }
    __syncthreads();

    const float4* va4 = reinterpret_cast<const float4*>(va);

    for (int gi = 0; gi < GQ; gi++) {
        const int m = blockIdx.x * GQ + gi;
        const int t0 = 4 * m;

        if (tid < 32) hh[tid] = g_h[(size_t)(t0 + 1 + (tid >> 3)) * HID + (tid & 7)];
        if (tid < SD) va[tid] = g_G[(size_t)m * SD + tid];
        __syncthreads();
#pragma unroll
        for (int s = 1; s <= 3; s++) {
            const int t = t0 + s;
            float cv = 0.f;
            if (tid < SD) {
                cv = matvec100(at4s, va4, tid)
                   + bwx * w[2 * (t - 1)] + bwy * w[2 * (t - 1) + 1]
                   + u[(size_t)(t - 1) * SD + tid] + db2;
#pragma unroll
                for (int z = 0; z < HID; z++) cv += w2r[z] * hh[8 * (s - 1) + z];
            }
            __syncthreads();
            if (tid < SD) {
                va[tid] = cv;
                outc[(size_t)(t - 1) * SD + tid] = cv;
            }
            __syncthreads();
            if (tid < NOBS) outy[(size_t)(t - 1) * NOBS + tid] = va[obsS[tid]];
        }
        // row t0+4 = anchor m+1
        __syncthreads();
        if (tid < SD) {
            float cv = g_G[(size_t)(m + 1) * SD + tid];
            va[tid] = cv;
            outc[(size_t)(t0 + 3) * SD + tid] = cv;
        }
        __syncthreads();
        if (tid < NOBS) outy[(size_t)(t0 + 3) * NOBS + tid] = va[obsS[tid]];
        __syncthreads();
    }
}

extern "C" void kernel_launch(void* const* d_in, const int* in_sizes, int n_in,
                              void* d_out, int out_size) {
    const float* c0  = (const float*)d_in[0];
    const float* w   = (const float*)d_in[1];
    const float* u   = (const float*)d_in[2];
    const float* A   = (const float*)d_in[3];
    const float* Bw  = (const float*)d_in[4];
    const float* W1  = (const float*)d_in[5];
    const float* b1  = (const float*)d_in[6];
    const float* W2  = (const float*)d_in[7];
    const float* b2  = (const float*)d_in[8];
    const int*   ob  = (const int*)d_in[9];

    float* outc = (float*)d_out;                      // (T, 100)
    float* outy = (float*)d_out + (size_t)TT * SD;    // (T, 12)

    setup1_kernel<<<1, 128>>>(A, Bw, W1, b1, W2, b2, c0, w, u);
    setup2_kernel<<<1, 128>>>(A, W1, W2);
    precomp_kernel<<<PRE_CTAS, 128>>>(w, u, Bw, W1, b1, b2);
    serial_kernel<<<1, 160>>>(c0);
    post_kernel<<<POST_CTAS, 128>>>(w, u, Bw, W2, b2, ob, outc, outy);
}